// round 5
// baseline (speedup 1.0000x reference)
#include <cuda_runtime.h>

#define BATCH 2048
#define IN_SZ 40960
#define HID 256
#define NF4 (BATCH * (IN_SZ / 4))
#define SCAN_CTAS 2048
#define SCAN_THREADS 256
#define SCAN_T (SCAN_CTAS * SCAN_THREADS)
#define SCAN_ITERS (NF4 / SCAN_T)
#define TR_BX (IN_SZ / 32)            // 1280 tile columns
#define TR_CTAS (TR_BX * (HID / 32))  // 10240 transpose tiles

__device__ float g_ftw_t[(size_t)IN_SZ * HID];   // 41.9 MB transposed weights
__device__ int   g_cnt[2][BATCH];                // zero-init; re-zeroed by gather_mlp
__device__ int   g_idx[2][BATCH][32];

// ---------------------------------------------------------------------------
// Kernel 1 (fused): blocks [0, SCAN_CTAS) stream-scan the one-hot arrays;
// blocks [SCAN_CTAS, SCAN_CTAS+TR_CTAS) transpose ft_w -> g_ftw_t.
// ---------------------------------------------------------------------------
__global__ __launch_bounds__(SCAN_THREADS) void scan_and_transpose(
    const float* __restrict__ white, const float* __restrict__ black,
    const float* __restrict__ ft_w)
{
    __shared__ float tile[32][33];
    const int tid = threadIdx.x;

    if (blockIdx.x < SCAN_CTAS) {
        // ---- streaming scan ----
        const int t = blockIdx.x * SCAN_THREADS + tid;
#pragma unroll
        for (int p = 0; p < 2; ++p) {
            const uint4* src = reinterpret_cast<const uint4*>(p ? black : white);
            for (int it = 0; it < SCAN_ITERS; it += 8) {
                uint4 f[8];
#pragma unroll
                for (int u = 0; u < 8; ++u)
                    f[u] = __ldcs(&src[t + (size_t)(it + u) * SCAN_T]);
#pragma unroll
                for (int u = 0; u < 8; ++u) {
                    if (f[u].x | f[u].y | f[u].z | f[u].w) {
                        int v    = t + (it + u) * SCAN_T;
                        int row  = v / (IN_SZ / 4);
                        int base = (v - row * (IN_SZ / 4)) * 4;
                        if (f[u].x) { int s = atomicAdd(&g_cnt[p][row], 1); g_idx[p][row][s] = base + 0; }
                        if (f[u].y) { int s = atomicAdd(&g_cnt[p][row], 1); g_idx[p][row][s] = base + 1; }
                        if (f[u].z) { int s = atomicAdd(&g_cnt[p][row], 1); g_idx[p][row][s] = base + 2; }
                        if (f[u].w) { int s = atomicAdd(&g_cnt[p][row], 1); g_idx[p][row][s] = base + 3; }
                    }
                }
            }
        }
    } else {
        // ---- transpose tile: ft_w [256, 40960] -> g_ftw_t [40960, 256] ----
        int bb = blockIdx.x - SCAN_CTAS;
        int bx = bb % TR_BX;
        int by = bb / TR_BX;
        int tx = tid & 31, ty = tid >> 5;   // 32 x 8
        int x = bx * 32 + tx;
        int y = by * 32 + ty;
#pragma unroll
        for (int k = 0; k < 32; k += 8)
            tile[ty + k][tx] = ft_w[(size_t)(y + k) * IN_SZ + x];
        __syncthreads();
        int ox = by * 32 + tx;
        int oy = bx * 32 + ty;
#pragma unroll
        for (int k = 0; k < 32; k += 8)
            g_ftw_t[(size_t)(oy + k) * HID + ox] = tile[tx][ty + k];
    }
}

// ---------------------------------------------------------------------------
// Kernel 2: float4 gather + fused MLP. One CTA per batch row.
// ---------------------------------------------------------------------------
__global__ __launch_bounds__(256) void gather_mlp(
    const float* __restrict__ stm,
    const float* __restrict__ ft_b,
    const float* __restrict__ l1w, const float* __restrict__ l1b,
    const float* __restrict__ l2w, const float* __restrict__ l2b,
    const float* __restrict__ l3w, const float* __restrict__ l3b,
    float* __restrict__ out)
{
    const int b   = blockIdx.x;
    const int tid = threadIdx.x;

    __shared__ int    widx[32], bidx[32];
    __shared__ int    cnts[2];
    __shared__ float4 red[2][4][64];
    __shared__ float  hid[2 * HID];
    __shared__ float  x1s[32];
    __shared__ float  x2s[32];

    if (tid < 32)      widx[tid]      = g_idx[0][b][tid];
    else if (tid < 64) bidx[tid - 32] = g_idx[1][b][tid - 32];
    // One thread per counter: read -> stash in shared -> zero (no cross-thread race).
    else if (tid == 64) { cnts[0] = g_cnt[0][b]; g_cnt[0][b] = 0; }
    else if (tid == 65) { cnts[1] = g_cnt[1][b]; g_cnt[1][b] = 0; }
    __syncthreads();

    const int wc = cnts[0];
    const int bc = cnts[1];

    const int c  = tid & 63;
    const int fg = tid >> 6;
    const float4* __restrict__ ftw4 = reinterpret_cast<const float4*>(g_ftw_t);

    float4 aw = make_float4(0.f, 0.f, 0.f, 0.f);
    float4 ab = make_float4(0.f, 0.f, 0.f, 0.f);
#pragma unroll 4
    for (int j = fg; j < wc; j += 4) {
        float4 v = ftw4[(size_t)widx[j] * 64 + c];
        aw.x += v.x; aw.y += v.y; aw.z += v.z; aw.w += v.w;
    }
#pragma unroll 4
    for (int j = fg; j < bc; j += 4) {
        float4 v = ftw4[(size_t)bidx[j] * 64 + c];
        ab.x += v.x; ab.y += v.y; ab.z += v.z; ab.w += v.w;
    }
    red[0][fg][c] = aw;
    red[1][fg][c] = ab;
    __syncthreads();

    const bool s = (stm[b] != 0.f);

    if (tid < 128) {
        int p  = tid >> 6;
        int cc = tid & 63;
        float4 v0 = red[p][0][cc], v1 = red[p][1][cc];
        float4 v2 = red[p][2][cc], v3 = red[p][3][cc];
        float4 bi = reinterpret_cast<const float4*>(ft_b)[cc];
        float4 r;
        r.x = fminf(fmaxf(v0.x + v1.x + v2.x + v3.x + bi.x, 0.f), 1.f);
        r.y = fminf(fmaxf(v0.y + v1.y + v2.y + v3.y + bi.y, 0.f), 1.f);
        r.z = fminf(fmaxf(v0.z + v1.z + v2.z + v3.z + bi.z, 0.f), 1.f);
        r.w = fminf(fmaxf(v0.w + v1.w + v2.w + v3.w + bi.w, 0.f), 1.f);
        int half = ((p == 0) == s) ? 0 : 1;
        reinterpret_cast<float4*>(hid)[half * 64 + cc] = r;
    }
    __syncthreads();

    // Layer 1: 512 -> 32, 8 threads per output, float4 loads
    {
        int k  = tid >> 3;
        int s8 = tid & 7;
        const float4* __restrict__ w4 = reinterpret_cast<const float4*>(l1w) + k * 128;
        const float4* h4 = reinterpret_cast<const float4*>(hid);
        float p = 0.f;
#pragma unroll
        for (int i = 0; i < 16; ++i) {
            float4 w = w4[s8 + 8 * i];
            float4 h = h4[s8 + 8 * i];
            p += w.x * h.x + w.y * h.y + w.z * h.z + w.w * h.w;
        }
        p += __shfl_down_sync(0xffffffffu, p, 4, 8);
        p += __shfl_down_sync(0xffffffffu, p, 2, 8);
        p += __shfl_down_sync(0xffffffffu, p, 1, 8);
        if (s8 == 0) x1s[k] = fminf(fmaxf(p + l1b[k], 0.f), 1.f);
    }
    __syncthreads();

    // Layer 2: 32 -> 32 (float4 loads)
    if (tid < 32) {
        const float4* w4 = reinterpret_cast<const float4*>(l2w) + tid * 8;
        const float4* x4 = reinterpret_cast<const float4*>(x1s);
        float p = l2b[tid];
#pragma unroll
        for (int i = 0; i < 8; ++i) {
            float4 w = w4[i];
            float4 x = x4[i];
            p += w.x * x.x + w.y * x.y + w.z * x.z + w.w * x.w;
        }
        x2s[tid] = fminf(fmaxf(p, 0.f), 1.f);
    }
    __syncwarp(0xffffffffu);

    // Layer 3: 32 -> 1
    if (tid < 32) {
        float p = x2s[tid] * l3w[tid];
        p += __shfl_down_sync(0xffffffffu, p, 16);
        p += __shfl_down_sync(0xffffffffu, p, 8);
        p += __shfl_down_sync(0xffffffffu, p, 4);
        p += __shfl_down_sync(0xffffffffu, p, 2);
        p += __shfl_down_sync(0xffffffffu, p, 1);
        if (tid == 0) out[b] = p + l3b[0];
    }
}

// ---------------------------------------------------------------------------
// Launch
// ---------------------------------------------------------------------------
extern "C" void kernel_launch(void* const* d_in, const int* in_sizes, int n_in,
                              void* d_out, int out_size) {
    const float* white = (const float*)d_in[0];
    const float* black = (const float*)d_in[1];
    const float* stm   = (const float*)d_in[2];
    const float* ft_w  = (const float*)d_in[3];
    const float* ft_b  = (const float*)d_in[4];
    const float* l1w   = (const float*)d_in[5];
    const float* l1b   = (const float*)d_in[6];
    const float* l2w   = (const float*)d_in[7];
    const float* l2b   = (const float*)d_in[8];
    const float* l3w   = (const float*)d_in[9];
    const float* l3b   = (const float*)d_in[10];
    float* out = (float*)d_out;

    scan_and_transpose<<<SCAN_CTAS + TR_CTAS, SCAN_THREADS>>>(white, black, ft_w);
    gather_mlp<<<BATCH, 256>>>(stm, ft_b, l1w, l1b, l2w, l2b, l3w, l3b, out);
}